// round 14
// baseline (speedup 1.0000x reference)
#include <cuda_runtime.h>
#include <cuda_fp16.h>
#include <cstdint>

// ---------------------------------------------------------------------------
// Problem constants
// ---------------------------------------------------------------------------
#define BATCH   2
#define SEQ     2048
#define DMODEL  2048
#define NHEADS  16
#define DH      128
#define NROWS   (BATCH*SEQ)              // 4096
#define CHUNK_E ((size_t)NROWS*DMODEL)

// Scratch (__device__ globals: allocation-free rule). All mma operands fp16.
__device__ __half g_q  [(size_t)BATCH*NHEADS*SEQ*DH];   // Q [B,H,S,Dh], scaled by log2e/sqrt(Dh)
__device__ __half g_ctx[(size_t)NROWS*DMODEL];          // attention ctx
__device__ __half g_wt [4ULL*DMODEL*DMODEL];            // W^T for q,k,v,o
__device__ __half g_x  [(size_t)NROWS*DMODEL];          // x
__device__ __half g_kr [(size_t)BATCH*NHEADS*SEQ*DH];   // K
__device__ __half g_vt [(size_t)BATCH*NHEADS*DH*SEQ];   // V^T [B,H,Dh,S]

// ---------------------------------------------------------------------------
// PTX helpers (baseline features only: work under compute_103)
// ---------------------------------------------------------------------------
__device__ __forceinline__ uint32_t smem_u32(const void* p) {
    uint32_t a;
    asm("{ .reg .u64 t; cvta.to.shared.u64 t, %1; cvt.u32.u64 %0, t; }"
        : "=r"(a) : "l"(p));
    return a;
}
#define CP_ASYNC16(dst, src) \
    asm volatile("cp.async.cg.shared.global [%0], [%1], 16;" :: "r"(dst), "l"(src))
#define CP_COMMIT()  asm volatile("cp.async.commit_group;" ::: "memory")
#define CP_WAIT1()   asm volatile("cp.async.wait_group 1;" ::: "memory")
#define CP_WAIT0()   asm volatile("cp.async.wait_group 0;" ::: "memory")

__device__ __forceinline__ void ldsm_x4(uint32_t& r0, uint32_t& r1,
                                        uint32_t& r2, uint32_t& r3, uint32_t a) {
    asm volatile("ldmatrix.sync.aligned.m8n8.x4.shared.b16 {%0,%1,%2,%3}, [%4];"
                 : "=r"(r0), "=r"(r1), "=r"(r2), "=r"(r3) : "r"(a));
}
// fp16 mma, fp32 accumulate: m16n8k16
__device__ __forceinline__ void mma_f16(float* c, const uint32_t* a,
                                        uint32_t b0, uint32_t b1) {
    asm volatile(
        "mma.sync.aligned.m16n8k16.row.col.f32.f16.f16.f32 "
        "{%0,%1,%2,%3},{%4,%5,%6,%7},{%8,%9},{%0,%1,%2,%3};"
        : "+f"(c[0]), "+f"(c[1]), "+f"(c[2]), "+f"(c[3])
        : "r"(a[0]), "r"(a[1]), "r"(a[2]), "r"(a[3]), "r"(b0), "r"(b1));
}
// two exps per MUFU op
__device__ __forceinline__ uint32_t h2exp2_(uint32_t x) {
    uint32_t r;
    asm("ex2.approx.f16x2 %0, %1;" : "=r"(r) : "r"(x));
    return r;
}

// ---------------------------------------------------------------------------
// fp32 -> fp16 copy (8 elems/thread)
// ---------------------------------------------------------------------------
__global__ __launch_bounds__(256) void tohalf_kernel(
    const float* __restrict__ in, __half* __restrict__ out)
{
    const int i = blockIdx.x * 256 + threadIdx.x;
    float4 v0 = ((const float4*)in)[2 * i];
    float4 v1 = ((const float4*)in)[2 * i + 1];
    half2 h[4];
    h[0] = __floats2half2_rn(v0.x, v0.y);
    h[1] = __floats2half2_rn(v0.z, v0.w);
    h[2] = __floats2half2_rn(v1.x, v1.y);
    h[3] = __floats2half2_rn(v1.z, v1.w);
    ((float4*)out)[i] = *(float4*)h;
}

// ---------------------------------------------------------------------------
// Fused 4-way weight transpose to fp16: out_z[n][k] = half(W_z[k][n])
// ---------------------------------------------------------------------------
__global__ __launch_bounds__(256) void transpose4_kernel(
    const float* __restrict__ W0, const float* __restrict__ W1,
    const float* __restrict__ W2, const float* __restrict__ W3,
    __half* __restrict__ outBase)
{
    __shared__ float t[32][33];
    const int z = blockIdx.z;
    const float* in = (z == 0) ? W0 : (z == 1) ? W1 : (z == 2) ? W2 : W3;
    __half* out = outBase + (size_t)z * DMODEL * DMODEL;

    const int x  = blockIdx.x * 32 + threadIdx.x;
    const int y0 = blockIdx.y * 32 + threadIdx.y;
    #pragma unroll
    for (int j = 0; j < 4; j++)
        t[threadIdx.y + j * 8][threadIdx.x] = in[(size_t)(y0 + j * 8) * DMODEL + x];
    __syncthreads();
    const int x2  = blockIdx.y * 32 + threadIdx.x;
    const int y20 = blockIdx.x * 32 + threadIdx.y;
    #pragma unroll
    for (int j = 0; j < 4; j++)
        out[(size_t)(y20 + j * 8) * DMODEL + x2] =
            __float2half_rn(t[threadIdx.x][threadIdx.y + j * 8]);
}

// ---------------------------------------------------------------------------
// fp16 mma GEMM mainloop: 128x128 CTA tile, BK=64, 3-stage cp.async ring.
//   Stage safety: compute stage p; chunk i+1 in (p+1)%3; prefetch i+2 into
//   (p+2)%3; top-of-loop __syncthreads orders reuse of stage p at i+1.
// ---------------------------------------------------------------------------
#define BK 64
#define NCHUNK (DMODEL / BK)          // 32
#define ROWB 144
#define TILE_B (128 * ROWB)           // 18432 bytes per matrix per stage
#define STAGE_B (2 * TILE_B)          // A+B per stage: 36864
#define GEMM_SMEM (3 * STAGE_B)       // 110592
#define TPAD 272                      // V^T staging row stride (bytes)

__device__ __forceinline__ void gemm_mainloop(
    const __half* __restrict__ Ab, const __half* __restrict__ Bb,
    uint32_t sb, int tid, float acc[4][4][4])
{
    const int wid = tid >> 5, lane = tid & 31;
    const int wm = wid & 1, wn = wid >> 1;
    const int r7 = lane & 7, sel = lane >> 3;

    const int grow = tid >> 1;            // 0..127
    const int gcolh = (tid & 1) * 32;     // halves (64B)

    const uint32_t aoff = (uint32_t)((wm * 64 + (sel & 1) * 8 + r7) * ROWB
                                   + (sel >> 1) * 16);
    const uint32_t boff = (uint32_t)((wn * 32 + (sel >> 1) * 8 + r7) * ROWB
                                   + (sel & 1) * 16);

    auto load_chunk = [&](int chunk, int p) {
        const __half* as = Ab + (size_t)grow * DMODEL + chunk * BK + gcolh;
        const __half* bs = Bb + (size_t)grow * DMODEL + chunk * BK + gcolh;
        const uint32_t ad = sb + p * STAGE_B          + grow * ROWB + gcolh * 2;
        const uint32_t bd = sb + p * STAGE_B + TILE_B + grow * ROWB + gcolh * 2;
        #pragma unroll
        for (int i = 0; i < 4; i++) {
            CP_ASYNC16(ad + i * 16, as + i * 8);
            CP_ASYNC16(bd + i * 16, bs + i * 8);
        }
    };

    #pragma unroll
    for (int mt = 0; mt < 4; mt++)
        #pragma unroll
        for (int nt = 0; nt < 4; nt++)
            #pragma unroll
            for (int q = 0; q < 4; q++) acc[mt][nt][q] = 0.f;

    load_chunk(0, 0); CP_COMMIT();
    load_chunk(1, 1); CP_COMMIT();

    int p = 0;   // stage of chunk i
    for (int i = 0; i < NCHUNK; i++) {
        if (i < NCHUNK - 1) { CP_WAIT1(); } else { CP_WAIT0(); }
        __syncthreads();
        if (i + 2 < NCHUNK) {
            int pn = p + 2; if (pn >= 3) pn -= 3;
            load_chunk(i + 2, pn);
            CP_COMMIT();
        }

        const uint32_t sa  = sb + p * STAGE_B + aoff;
        const uint32_t sbb = sb + p * STAGE_B + TILE_B + boff;
        #pragma unroll
        for (int ks = 0; ks < 4; ks++) {          // k16 steps
            uint32_t a[4][4], b[2][4];
            #pragma unroll
            for (int mt = 0; mt < 4; mt++)
                ldsm_x4(a[mt][0], a[mt][1], a[mt][2], a[mt][3],
                        sa + mt * 16 * ROWB + ks * 32);
            #pragma unroll
            for (int np = 0; np < 2; np++)
                ldsm_x4(b[np][0], b[np][1], b[np][2], b[np][3],
                        sbb + np * 16 * ROWB + ks * 32);
            #pragma unroll
            for (int mt = 0; mt < 4; mt++)
                #pragma unroll
                for (int nt = 0; nt < 4; nt++)
                    mma_f16(acc[mt][nt], a[mt],
                            b[nt >> 1][(nt & 1) * 2], b[nt >> 1][(nt & 1) * 2 + 1]);
        }
        if (++p == 3) p = 0;
    }
}

// ---------------------------------------------------------------------------
// Fused Q/K/V projection GEMM. z: 0=Q (half out, log2e-scaled), 1=K (fp32 +
// half), 2=V (fp32 out + fused transposed fp16 V^T via smem staging).
// ---------------------------------------------------------------------------
__global__ __launch_bounds__(256, 2) void gemm_qkv_kernel(
    const __half* __restrict__ A, const __half* __restrict__ WtBase,
    const float* __restrict__ bq, const float* __restrict__ bk,
    const float* __restrict__ bv,
    __half* __restrict__ Cq, float* __restrict__ Ck, float* __restrict__ Cv,
    __half* __restrict__ Ck2, __half* __restrict__ Vt, float qscale)
{
    extern __shared__ char smc[];
    const uint32_t sb = smem_u32(smc);
    const int tid = threadIdx.x;
    const int wid = tid >> 5, lane = tid & 31;
    const int bx = blockIdx.x, by = blockIdx.y, z = blockIdx.z;

    const __half* Bt  = WtBase + (size_t)z * DMODEL * DMODEL;
    const float* bias = (z == 0) ? bq : (z == 1) ? bk : bv;

    const __half* Ab = A  + (size_t)(by * 128) * DMODEL;
    const __half* Bb = Bt + (size_t)(bx * 128) * DMODEL;

    float acc[4][4][4];
    gemm_mainloop(Ab, Bb, sb, tid, acc);

    const int wm = wid & 1, wn = wid >> 1;
    const int qr = lane >> 2, qc = (lane & 3) * 2;
    #pragma unroll
    for (int nt = 0; nt < 4; nt++) {
        const int dh = wn * 32 + nt * 8 + qc;
        const float bv0 = bias[bx * 128 + dh];
        const float bv1 = bias[bx * 128 + dh + 1];
        #pragma unroll
        for (int mt = 0; mt < 4; mt++) {
            #pragma unroll
            for (int half_ = 0; half_ < 2; half_++) {
                const int mrow = by * 128 + wm * 64 + mt * 16 + half_ * 8 + qr;
                const int b = mrow >> 11, s = mrow & 2047;
                const size_t idx = (((size_t)(b * NHEADS + bx) * SEQ + s) * DH) + dh;
                float r0 = acc[mt][nt][half_ * 2 + 0] + bv0;
                float r1 = acc[mt][nt][half_ * 2 + 1] + bv1;
                if (z == 0) {
                    *(half2*)(Cq + idx) = __floats2half2_rn(r0 * qscale, r1 * qscale);
                } else if (z == 1) {
                    *(float2*)(Ck + idx) = make_float2(r0, r1);
                    *(half2*)(Ck2 + idx) = __floats2half2_rn(r0, r1);
                } else {
                    *(float2*)(Cv + idx) = make_float2(r0, r1);
                }
            }
        }
    }

    // ---- z==2: fused V^T (fp16) via smem transpose staging ----
    if (z == 2) {
        __syncthreads();   // mainloop smem fully released by all warps
        #pragma unroll
        for (int nt = 0; nt < 4; nt++) {
            const int dh = wn * 32 + nt * 8 + qc;
            const float bv0 = bias[bx * 128 + dh];
            const float bv1 = bias[bx * 128 + dh + 1];
            #pragma unroll
            for (int mt = 0; mt < 4; mt++) {
                #pragma unroll
                for (int half_ = 0; half_ < 2; half_++) {
                    const int sl = wm * 64 + mt * 16 + half_ * 8 + qr;
                    *(__half*)(smc + dh * TPAD + sl * 2) =
                        __float2half_rn(acc[mt][nt][half_ * 2 + 0] + bv0);
                    *(__half*)(smc + (dh + 1) * TPAD + sl * 2) =
                        __float2half_rn(acc[mt][nt][half_ * 2 + 1] + bv1);
                }
            }
        }
        __syncthreads();
        const int b = by >> 4, s0 = (by & 15) * 128;
        __half* vtb = Vt + ((size_t)(b * NHEADS + bx) * DH) * SEQ + s0;
        #pragma unroll
        for (int i = 0; i < 8; i++) {
            const int idx = i * 256 + tid;
            const int row = idx >> 4, c = idx & 15;     // row=dh, 16B chunks
            *(float4*)(vtb + (size_t)row * SEQ + c * 8) =
                *(const float4*)(smc + row * TPAD + c * 16);
        }
    }
}

// ---------------------------------------------------------------------------
// Output projection GEMM: C = ctx(half) @ Wo^T(half) + bo, fp32 row-major out
// ---------------------------------------------------------------------------
__global__ __launch_bounds__(256, 2) void gemm_o_kernel(
    const __half* __restrict__ A, const __half* __restrict__ Bt,
    const float* __restrict__ bias, float* __restrict__ C)
{
    extern __shared__ char smc[];
    const uint32_t sb = smem_u32(smc);
    const int tid = threadIdx.x;
    const int wid = tid >> 5, lane = tid & 31;
    const int bx = blockIdx.x, by = blockIdx.y;

    const __half* Ab = A  + (size_t)(by * 128) * DMODEL;
    const __half* Bb = Bt + (size_t)(bx * 128) * DMODEL;

    float acc[4][4][4];
    gemm_mainloop(Ab, Bb, sb, tid, acc);

    const int wm = wid & 1, wn = wid >> 1;
    const int qr = lane >> 2, qc = (lane & 3) * 2;
    #pragma unroll
    for (int nt = 0; nt < 4; nt++) {
        const int dh = wn * 32 + nt * 8 + qc;
        const float bv0 = bias[bx * 128 + dh];
        const float bv1 = bias[bx * 128 + dh + 1];
        #pragma unroll
        for (int mt = 0; mt < 4; mt++) {
            #pragma unroll
            for (int half_ = 0; half_ < 2; half_++) {
                const int mrow = by * 128 + wm * 64 + mt * 16 + half_ * 8 + qr;
                float2 r;
                r.x = acc[mt][nt][half_ * 2 + 0] + bv0;
                r.y = acc[mt][nt][half_ * 2 + 1] + bv1;
                *(float2*)(C + (size_t)mrow * DMODEL + bx * 128 + dh) = r;
            }
        }
    }
}

// ---------------------------------------------------------------------------
// fp16 tensor-core causal flash attention. Heavy-first CTA order.
//   Scores in log2 domain (log2e folded into Q); softmax via ex2.approx.f16x2
//   (2 exps per MUFU op); P written fp16, l accumulated from the SAME fp16 P.
// ---------------------------------------------------------------------------
#define BQ 128
#define BJ 64
#define QROWB 272
#define VROWB 144
#define PROWB 144
#define QS_B     (128 * QROWB)                     // 34816
#define SK_OFF(p) (QS_B + (p) * (BJ * QROWB))
#define SV_OFF(p) (QS_B + 2 * (BJ * QROWB) + (p) * (DH * VROWB))
#define PS_OFF    (QS_B + 2 * (BJ * QROWB) + 2 * (DH * VROWB))
#define ATTN2_SMEM (PS_OFF + BQ * PROWB)           // 124928

__global__ __launch_bounds__(256, 1) void attn_tc_kernel(
    const __half* __restrict__ Kr, const __half* __restrict__ Vt)
{
    extern __shared__ char smc[];
    const uint32_t sb = smem_u32(smc);
    const int tid = threadIdx.x, wid = tid >> 5, lane = tid & 31;
    const int qb = gridDim.x - 1 - blockIdx.x;      // heavy CTAs first
    const int h = blockIdx.y, b = blockIdx.z;
    const int q0 = qb * BQ;
    const int wq = wid * 16;
    const int r7 = lane & 7, sel = lane >> 3;
    const int qr = lane >> 2, qc2 = (lane & 3) * 2;

    const size_t headoff = (size_t)(b * NHEADS + h) * SEQ * DH;
    const __half* qbase  = g_q + headoff;
    const __half* kbase  = Kr  + headoff;
    const __half* vtbase = Vt  + (size_t)(b * NHEADS + h) * DH * SEQ;

    auto prefetch = [&](int t, int p) {
        const int j0 = t * BJ;
        {   // K tile: 64 rows x 128 halves (256B)
            const __half* src = kbase + (size_t)(j0 + (tid >> 2)) * DH + (tid & 3) * 32;
            const uint32_t dst = sb + SK_OFF(p) + (tid >> 2) * QROWB + (tid & 3) * 64;
            #pragma unroll
            for (int i = 0; i < 4; i++) CP_ASYNC16(dst + i * 16, src + i * 8);
        }
        {   // V^T tile: 128 rows x 64 halves (128B)
            const __half* src = vtbase + (size_t)(tid >> 1) * SEQ + j0 + (tid & 1) * 32;
            const uint32_t dst = sb + SV_OFF(p) + (tid >> 1) * VROWB + (tid & 1) * 64;
            #pragma unroll
            for (int i = 0; i < 4; i++) CP_ASYNC16(dst + i * 16, src + i * 8);
        }
    };

    // overlap tile-0 prefetch with Q staging
    prefetch(0, 0); CP_COMMIT();

    // stage Q (already fp16) into smem
    #pragma unroll
    for (int i = 0; i < 8; i++) {
        const int idx = i * 256 + tid;              // 2048 float4-chunks
        const int row = idx >> 4, c = idx & 15;     // 16 x 16B per 256B row
        *(float4*)(smc + row * QROWB + c * 16) =
            *(const float4*)(qbase + (size_t)(q0 + row) * DH + c * 8);
    }
    __syncthreads();
    uint32_t qf[8][4];
    {
        const uint32_t ab = sb + (wq + (sel & 1) * 8 + r7) * QROWB + (sel >> 1) * 16;
        #pragma unroll
        for (int ks = 0; ks < 8; ks++)
            ldsm_x4(qf[ks][0], qf[ks][1], qf[ks][2], qf[ks][3], ab + ks * 32);
    }

    float oacc[16][4];
    #pragma unroll
    for (int nt = 0; nt < 16; nt++)
        #pragma unroll
        for (int q = 0; q < 4; q++) oacc[nt][q] = 0.f;
    float m[2] = {-1e30f, -1e30f}, l[2] = {0.f, 0.f};

    const int ntiles = 2 * qb + 2;
    for (int t = 0; t < ntiles; t++) {
        const int p = t & 1;
        __syncthreads();
        if (t + 1 < ntiles) { prefetch(t + 1, 1 - p); CP_COMMIT(); CP_WAIT1(); }
        else                { CP_WAIT0(); }
        __syncthreads();

        const int j0 = t * BJ;
        if (j0 > q0 + wq + 15) continue;

        // ---- S = Q K^T in log2 domain (8 k16-steps over Dh) ----
        float sacc[8][4];
        #pragma unroll
        for (int nt = 0; nt < 8; nt++)
            #pragma unroll
            for (int q = 0; q < 4; q++) sacc[nt][q] = 0.f;

        const uint32_t kb0 = sb + SK_OFF(p)
                           + ((sel >> 1) * 8 + r7) * QROWB + (sel & 1) * 16;
        #pragma unroll
        for (int ks = 0; ks < 8; ks++) {
            #pragma unroll
            for (int np = 0; np < 4; np++) {
                uint32_t b0, b1, b2, b3;
                ldsm_x4(b0, b1, b2, b3, kb0 + np * 16 * QROWB + ks * 32);
                mma_f16(sacc[2 * np],     qf[ks], b0, b1);
                mma_f16(sacc[2 * np + 1], qf[ks], b2, b3);
            }
        }

        // ---- causal mask ----
        const int row0 = q0 + wq + qr;
        if (j0 + BJ - 1 > q0 + wq) {
            #pragma unroll
            for (int nt = 0; nt < 8; nt++) {
                const int c0 = j0 + nt * 8 + qc2;
                if (c0     > row0)     sacc[nt][0] = -1e30f;
                if (c0 + 1 > row0)     sacc[nt][1] = -1e30f;
                if (c0     > row0 + 8) sacc[nt][2] = -1e30f;
                if (c0 + 1 > row0 + 8) sacc[nt][3] = -1e30f;
            }
        }

        // ---- online softmax (2 rows per thread); P in fp16 via ex2.f16x2 ----
        #pragma unroll
        for (int r = 0; r < 2; r++) {
            float rmax = -1e30f;
            #pragma unroll
            for (int nt = 0; nt < 8; nt++)
                rmax = fmaxf(rmax, fmaxf(sacc[nt][2 * r], sacc[nt][2 * r + 1]));
            rmax = fmaxf(rmax, __shfl_xor_sync(0xffffffffu, rmax, 1));
            rmax = fmaxf(rmax, __shfl_xor_sync(0xffffffffu, rmax, 2));
            const float mnew  = fmaxf(m[r], rmax);
            const float alpha = exp2f(m[r] - mnew);

            const uint32_t pbo = PS_OFF + (wq + r * 8 + qr) * PROWB + qc2 * 2;
            float rsum = 0.f;
            #pragma unroll
            for (int nt = 0; nt < 8; nt++) {
                half2 din = __floats2half2_rn(sacc[nt][2 * r]     - mnew,
                                              sacc[nt][2 * r + 1] - mnew);
                uint32_t pu = h2exp2_(*(uint32_t*)&din);
                *(uint32_t*)(smc + pbo + nt * 16) = pu;
                float2 pf = __half22float2(*(half2*)&pu);
                rsum += pf.x + pf.y;
            }
            rsum += __shfl_xor_sync(0xffffffffu, rsum, 1);
            rsum += __shfl_xor_sync(0xffffffffu, rsum, 2);
            l[r] = l[r] * alpha + rsum;
            m[r] = mnew;
            if (alpha != 1.f) {
                #pragma unroll
                for (int nt = 0; nt < 16; nt++) {
                    oacc[nt][2 * r]     *= alpha;
                    oacc[nt][2 * r + 1] *= alpha;
                }
            }
        }
        __syncwarp();

        // ---- O += P V (4 k16-steps over BJ) ----
        const uint32_t pab = sb + PS_OFF
                           + (wq + (sel & 1) * 8 + r7) * PROWB + (sel >> 1) * 16;
        const uint32_t vb0 = sb + SV_OFF(p)
                           + ((sel >> 1) * 8 + r7) * VROWB + (sel & 1) * 16;
        #pragma unroll
        for (int ks = 0; ks < 4; ks++) {
            uint32_t pa[4];
            ldsm_x4(pa[0], pa[1], pa[2], pa[3], pab + ks * 32);
            #pragma unroll
            for (int np = 0; np < 8; np++) {
                uint32_t b0, b1, b2, b3;
                ldsm_x4(b0, b1, b2, b3, vb0 + np * 16 * VROWB + ks * 32);
                mma_f16(oacc[2 * np],     pa, b0, b1);
                mma_f16(oacc[2 * np + 1], pa, b2, b3);
            }
        }
    }

    // ---- epilogue: O /= l, write ctx (fp16, feeds o-GEMM) ----
    const float inv0 = 1.f / l[0], inv1 = 1.f / l[1];
    __half* crow0 = g_ctx + (size_t)(b * SEQ + q0 + wq + qr) * DMODEL + h * DH + qc2;
    __half* crow1 = crow0 + 8 * DMODEL;
    #pragma unroll
    for (int nt = 0; nt < 16; nt++) {
        *(half2*)(crow0 + nt * 8) = __floats2half2_rn(oacc[nt][0] * inv0,
                                                      oacc[nt][1] * inv0);
        *(half2*)(crow1 + nt * 8) = __floats2half2_rn(oacc[nt][2] * inv1,
                                                      oacc[nt][3] * inv1);
    }
}

// ---------------------------------------------------------------------------
// Residual + LayerNorm
// ---------------------------------------------------------------------------
__global__ __launch_bounds__(256) void ln_kernel(
    const float* __restrict__ x, const float* __restrict__ ao,
    const float* __restrict__ gamma, const float* __restrict__ beta,
    float* __restrict__ out)
{
    __shared__ float ys[DMODEL];
    __shared__ float s_part[16];
    __shared__ float s_mu, s_rstd;

    const int r = blockIdx.x;
    const int t = threadIdx.x;
    const float* xr = x + (size_t)r * DMODEL;
    const float* ar = ao + (size_t)r * DMODEL;

    float sum = 0.f, sq = 0.f;
    for (int d = t; d < DMODEL; d += 256) {
        float y = xr[d] + ar[d];
        ys[d] = y;
        sum += y;
        sq  += y * y;
    }
    #pragma unroll
    for (int off = 16; off > 0; off >>= 1) {
        sum += __shfl_xor_sync(0xffffffffu, sum, off);
        sq  += __shfl_xor_sync(0xffffffffu, sq, off);
    }
    const int wid = t >> 5, lane = t & 31;
    if (lane == 0) { s_part[wid] = sum; s_part[8 + wid] = sq; }
    __syncthreads();
    if (t == 0) {
        float S = 0.f, Q = 0.f;
        #pragma unroll
        for (int w = 0; w < 8; w++) { S += s_part[w]; Q += s_part[8 + w]; }
        float mu  = S * (1.f / DMODEL);
        float var = Q * (1.f / DMODEL) - mu * mu;
        s_mu = mu;
        s_rstd = rsqrtf(var + 1e-5f);
    }
    __syncthreads();
    const float mu = s_mu, rstd = s_rstd;
    float* outr = out + (size_t)r * DMODEL;
    for (int d = t; d < DMODEL; d += 256)
        outr[d] = gamma[d] * (ys[d] - mu) * rstd + beta[d];
}

// ---------------------------------------------------------------------------
extern "C" void kernel_launch(void* const* d_in, const int* in_sizes, int n_in,
                              void* d_out, int out_size)
{
    const float* x     = (const float*)d_in[0];
    const float* Wq    = (const float*)d_in[1];
    const float* bq    = (const float*)d_in[2];
    const float* Wk    = (const float*)d_in[3];
    const float* bk    = (const float*)d_in[4];
    const float* Wv    = (const float*)d_in[5];
    const float* bv    = (const float*)d_in[6];
    const float* Wo    = (const float*)d_in[7];
    const float* bo    = (const float*)d_in[8];
    const float* gamma = (const float*)d_in[9];
    const float* beta  = (const float*)d_in[10];

    float* out    = (float*)d_out;
    float* ln_out = out;
    float* ao_out = out + CHUNK_E;
    float* k_out  = out + 2 * CHUNK_E;   // [B,H,S,Dh]
    float* v_out  = out + 3 * CHUNK_E;   // [B,H,S,Dh]

    __half *qptr = nullptr, *ctxptr = nullptr, *wtptr = nullptr, *xptr = nullptr;
    __half *krptr = nullptr, *vtptr = nullptr;
    cudaGetSymbolAddress((void**)&qptr,   g_q);
    cudaGetSymbolAddress((void**)&ctxptr, g_ctx);
    cudaGetSymbolAddress((void**)&wtptr,  g_wt);
    cudaGetSymbolAddress((void**)&xptr,   g_x);
    cudaGetSymbolAddress((void**)&krptr,  g_kr);
    cudaGetSymbolAddress((void**)&vtptr,  g_vt);
    __half* wt_o = wtptr + 3ULL * DMODEL * DMODEL;

    cudaFuncSetAttribute(gemm_qkv_kernel,
                         cudaFuncAttributeMaxDynamicSharedMemorySize, GEMM_SMEM);
    cudaFuncSetAttribute(gemm_o_kernel,
                         cudaFuncAttributeMaxDynamicSharedMemorySize, GEMM_SMEM);
    cudaFuncSetAttribute(attn_tc_kernel,
                         cudaFuncAttributeMaxDynamicSharedMemorySize, ATTN2_SMEM);

    // x -> fp16; fused 4-way W^T transpose to fp16 (order: q,k,v,o)
    tohalf_kernel<<<(int)(CHUNK_E / 8 / 256), 256>>>(x, xptr);
    dim3 tg(DMODEL / 32, DMODEL / 32, 4), tb(32, 8);
    transpose4_kernel<<<tg, tb>>>(Wq, Wk, Wv, Wo, wtptr);

    // log2(e)/sqrt(Dh): scores land directly in the log2 domain
    const float qscale = 0.08838834764831845f * 1.4426950408889634f;

    // Fused Q/K/V projections (V^T produced in the z==2 epilogue)
    dim3 qkv_grid(DMODEL / 128, NROWS / 128, 3);
    gemm_qkv_kernel<<<qkv_grid, 256, GEMM_SMEM>>>(
        xptr, wtptr, bq, bk, bv, qptr, k_out, v_out, krptr, vtptr, qscale);

    dim3 attn_grid(SEQ / BQ, NHEADS, BATCH);
    attn_tc_kernel<<<attn_grid, 256, ATTN2_SMEM>>>(krptr, vtptr);

    dim3 o_grid(DMODEL / 128, NROWS / 128);
    gemm_o_kernel<<<o_grid, 256, GEMM_SMEM>>>(ctxptr, wt_o, bo, ao_out);

    ln_kernel<<<NROWS, 256>>>(x, ao_out, gamma, beta, ln_out);
}